// round 2
// baseline (speedup 1.0000x reference)
#include <cuda_runtime.h>
#include <math.h>

// Problem constants
#define Bq   16
#define Nq   576
#define Cq   768
#define Hq   12
#define DHq  64
#define IMGq 24

// d_out layout (floats): out [B,N,C] | attn [B,H,N,N] | v [B,H,N,Dh]
#define OFF_ATTN 7077888
#define OFF_V    70778880

// Scratch (device globals; allocation-free rule)
__device__ float g_q[Bq * Hq * Nq * DHq];    // [B,H,N,Dh]
__device__ float g_k[Bq * Hq * Nq * DHq];    // [B,H,N,Dh]
__device__ float g_ctx[Bq * Nq * Cq];        // [B,N,C] (h*64+d inner)
__device__ float g_pos[Hq * Nq * Nq];        // [H,N,N] softmaxed positional scores

// ---------------------------------------------------------------------------
// Positional scores: logit(h,n,m) = dx*w0 + dy*w1 + (dx^2+dy^2)*w2 + b ; softmax over m
// one block per (n,h); 256 threads each own m = t, t+256, t+512(<576)
// ---------------------------------------------------------------------------
__global__ __launch_bounds__(256) void pos_kernel(const float* __restrict__ wpos,
                                                  const float* __restrict__ bpos)
{
    int n = blockIdx.x;
    int h = blockIdx.y;
    int t = threadIdx.x;
    __shared__ float red[8];

    int nx = n % IMGq, ny = n / IMGq;
    float w0 = wpos[h], w1 = wpos[Hq + h], w2 = wpos[2 * Hq + h], bb = bpos[h];

    auto logit = [&](int m) {
        float dx = (float)(m % IMGq - nx);
        float dy = (float)(m / IMGq - ny);
        return dx * w0 + dy * w1 + (dx * dx + dy * dy) * w2 + bb;
    };

    float l0 = logit(t);
    float l1 = logit(t + 256);
    float l2 = (t < 64) ? logit(t + 512) : -1e30f;

    float mx = fmaxf(fmaxf(l0, l1), l2);
    #pragma unroll
    for (int o = 16; o; o >>= 1) mx = fmaxf(mx, __shfl_xor_sync(0xFFFFFFFFu, mx, o));
    if ((t & 31) == 0) red[t >> 5] = mx;
    __syncthreads();
    float bm = red[0];
    #pragma unroll
    for (int i = 1; i < 8; ++i) bm = fmaxf(bm, red[i]);
    __syncthreads();

    float e0 = expf(l0 - bm);
    float e1 = expf(l1 - bm);
    float e2 = (t < 64) ? expf(l2 - bm) : 0.0f;
    float s = e0 + e1 + e2;
    #pragma unroll
    for (int o = 16; o; o >>= 1) s += __shfl_xor_sync(0xFFFFFFFFu, s, o);
    if ((t & 31) == 0) red[t >> 5] = s;
    __syncthreads();
    float ts = 0.0f;
    #pragma unroll
    for (int i = 0; i < 8; ++i) ts += red[i];
    float inv = 1.0f / ts;

    float* dst = g_pos + ((size_t)h * Nq + n) * Nq;
    dst[t] = e0 * inv;
    dst[t + 256] = e1 * inv;
    if (t < 64) dst[t + 512] = e2 * inv;
}

// ---------------------------------------------------------------------------
// SGEMM 128x128x8, 256 threads, 8x8 microtile. A = x [9216 x 768] row-major.
// B columns 0..1535 -> w_qk, 1536..2303 -> w_v. Epilogue scatters q,k,v.
// ---------------------------------------------------------------------------
__global__ __launch_bounds__(256) void gemm_qkv_kernel(const float* __restrict__ X,
                                                       const float* __restrict__ Wqk,
                                                       const float* __restrict__ Wv,
                                                       float* __restrict__ dout)
{
    __shared__ float As[8][132];   // transposed A tile, padded
    __shared__ float Bs[8][128];

    int tid = threadIdx.x;
    int rowTile = blockIdx.y;        // 0..71
    int col0 = blockIdx.x * 128;     // 0..2176

    const float* Bp; int ldb; int cb;
    if (col0 < 1536) { Bp = Wqk; ldb = 1536; cb = col0; }
    else             { Bp = Wv;  ldb = 768;  cb = col0 - 1536; }

    int arow = tid >> 1;
    int acol = (tid & 1) * 4;
    int brow = tid >> 5;
    int bcol = (tid & 31) * 4;

    const float* Aptr = X + (size_t)(rowTile * 128 + arow) * Cq + acol;
    const float* Bptr = Bp + (size_t)brow * ldb + cb + bcol;

    float acc[8][8];
    #pragma unroll
    for (int i = 0; i < 8; ++i)
        #pragma unroll
        for (int j = 0; j < 8; ++j) acc[i][j] = 0.0f;

    int ty = tid >> 4, tx = tid & 15;

    for (int kt = 0; kt < Cq / 8; ++kt) {
        float4 av = *(const float4*)(Aptr + kt * 8);
        As[acol + 0][arow] = av.x;
        As[acol + 1][arow] = av.y;
        As[acol + 2][arow] = av.z;
        As[acol + 3][arow] = av.w;
        *(float4*)&Bs[brow][bcol] = *(const float4*)(Bptr + (size_t)(kt * 8) * ldb);
        __syncthreads();

        #pragma unroll
        for (int kk = 0; kk < 8; ++kk) {
            float4 a0 = *(const float4*)&As[kk][ty * 8];
            float4 a1 = *(const float4*)&As[kk][ty * 8 + 4];
            float4 b0 = *(const float4*)&Bs[kk][tx * 8];
            float4 b1 = *(const float4*)&Bs[kk][tx * 8 + 4];
            float a[8] = {a0.x, a0.y, a0.z, a0.w, a1.x, a1.y, a1.z, a1.w};
            float bv[8] = {b0.x, b0.y, b0.z, b0.w, b1.x, b1.y, b1.z, b1.w};
            #pragma unroll
            for (int i = 0; i < 8; ++i)
                #pragma unroll
                for (int j = 0; j < 8; ++j)
                    acc[i][j] = fmaf(a[i], bv[j], acc[i][j]);
        }
        __syncthreads();
    }

    // scatter epilogue
    #pragma unroll
    for (int i = 0; i < 8; ++i) {
        int gm = rowTile * 128 + ty * 8 + i;
        int bi = gm / Nq;
        int n  = gm - bi * Nq;
        #pragma unroll
        for (int j = 0; j < 8; ++j) {
            int gn = col0 + tx * 8 + j;
            float val = acc[i][j];
            if (gn < 768) {
                int h = gn >> 6, d = gn & 63;
                g_q[(((size_t)bi * Hq + h) * Nq + n) * DHq + d] = val;
            } else if (gn < 1536) {
                int r = gn - 768; int h = r >> 6, d = r & 63;
                g_k[(((size_t)bi * Hq + h) * Nq + n) * DHq + d] = val;
            } else {
                int r = gn - 1536; int h = r >> 6, d = r & 63;
                dout[OFF_V + (((size_t)bi * Hq + h) * Nq + n) * DHq + d] = val;
            }
        }
    }
}

// ---------------------------------------------------------------------------
// Projection GEMM: g_ctx [9216 x 768] @ w_proj [768 x 768] + b_proj -> dout[0..]
// ---------------------------------------------------------------------------
__global__ __launch_bounds__(256) void gemm_proj_kernel(const float* __restrict__ Wp,
                                                        const float* __restrict__ bp,
                                                        float* __restrict__ dout)
{
    __shared__ float As[8][132];
    __shared__ float Bs[8][128];

    int tid = threadIdx.x;
    int rowTile = blockIdx.y;       // 0..71
    int col0 = blockIdx.x * 128;    // 0..640

    int arow = tid >> 1;
    int acol = (tid & 1) * 4;
    int brow = tid >> 5;
    int bcol = (tid & 31) * 4;

    const float* Aptr = g_ctx + (size_t)(rowTile * 128 + arow) * Cq + acol;
    const float* Bptr = Wp + (size_t)brow * Cq + col0 + bcol;

    float acc[8][8];
    #pragma unroll
    for (int i = 0; i < 8; ++i)
        #pragma unroll
        for (int j = 0; j < 8; ++j) acc[i][j] = 0.0f;

    int ty = tid >> 4, tx = tid & 15;

    for (int kt = 0; kt < Cq / 8; ++kt) {
        float4 av = *(const float4*)(Aptr + kt * 8);
        As[acol + 0][arow] = av.x;
        As[acol + 1][arow] = av.y;
        As[acol + 2][arow] = av.z;
        As[acol + 3][arow] = av.w;
        *(float4*)&Bs[brow][bcol] = *(const float4*)(Bptr + (size_t)(kt * 8) * Cq);
        __syncthreads();

        #pragma unroll
        for (int kk = 0; kk < 8; ++kk) {
            float4 a0 = *(const float4*)&As[kk][ty * 8];
            float4 a1 = *(const float4*)&As[kk][ty * 8 + 4];
            float4 b0 = *(const float4*)&Bs[kk][tx * 8];
            float4 b1 = *(const float4*)&Bs[kk][tx * 8 + 4];
            float a[8] = {a0.x, a0.y, a0.z, a0.w, a1.x, a1.y, a1.z, a1.w};
            float bv[8] = {b0.x, b0.y, b0.z, b0.w, b1.x, b1.y, b1.z, b1.w};
            #pragma unroll
            for (int i = 0; i < 8; ++i)
                #pragma unroll
                for (int j = 0; j < 8; ++j)
                    acc[i][j] = fmaf(a[i], bv[j], acc[i][j]);
        }
        __syncthreads();
    }

    #pragma unroll
    for (int i = 0; i < 8; ++i) {
        int gm = rowTile * 128 + ty * 8 + i;
        #pragma unroll
        for (int j = 0; j < 8; ++j) {
            int gn = col0 + tx * 8 + j;
            dout[(size_t)gm * Cq + gn] = acc[i][j] + bp[gn];
        }
    }
}

// ---------------------------------------------------------------------------
// Fused attention: per (qtile of 32, h, b):
//   S = Q Kt * scale -> softmax -> blend with pos via sigmoid gate -> renorm
//   -> write attn to d_out -> ctx = attn @ V -> g_ctx
// Dynamic smem: qs[32][68] + kv[64][68] + ss[32][580]  = 100,352 bytes
// ---------------------------------------------------------------------------
#define SMEM_ATTN_BYTES ((32 * 68 + 64 * 68 + 32 * 580) * 4)

__global__ __launch_bounds__(256) void attn_kernel(const float* __restrict__ gating,
                                                   float* __restrict__ dout)
{
    extern __shared__ float sm[];
    float* qs = sm;                 // 32 x 68
    float* kv = sm + 32 * 68;       // 64 x 68
    float* ss = sm + 32 * 68 + 64 * 68;  // 32 x 580
    __shared__ float sinv[32];

    int t  = threadIdx.x;
    int qt = blockIdx.x;    // 0..17
    int h  = blockIdx.y;    // 0..11
    int b  = blockIdx.z;    // 0..15
    int n0 = qt * 32;

    const float* qg = g_q + (((size_t)b * Hq + h) * Nq + n0) * DHq;
    const float* kg = g_k + (((size_t)b * Hq + h) * Nq) * DHq;
    const float* vg = dout + OFF_V + (((size_t)b * Hq + h) * Nq) * DHq;

    // load Q tile (2048 floats)
    #pragma unroll
    for (int it = 0; it < 8; ++it) {
        int idx = t + 256 * it;
        int r = idx >> 6, d = idx & 63;
        qs[r * 68 + d] = qg[idx];
    }

    // ---- scores: S[32 x 576], thread microtile = 4 rows x 2 keys ----
    int r0 = (t >> 5) * 4;
    int c0 = (t & 31) * 2;
    for (int kt = 0; kt < 9; ++kt) {
        __syncthreads();
        #pragma unroll
        for (int it = 0; it < 16; ++it) {
            int idx = t + 256 * it;
            int r = idx >> 6, d = idx & 63;
            kv[r * 68 + d] = kg[(size_t)kt * 4096 + idx];
        }
        __syncthreads();

        float acc[4][2];
        #pragma unroll
        for (int i = 0; i < 4; ++i) { acc[i][0] = 0.0f; acc[i][1] = 0.0f; }

        #pragma unroll
        for (int kk = 0; kk < 64; kk += 4) {
            float4 k0 = *(const float4*)&kv[c0 * 68 + kk];
            float4 k1 = *(const float4*)&kv[(c0 + 1) * 68 + kk];
            #pragma unroll
            for (int i = 0; i < 4; ++i) {
                float4 qv = *(const float4*)&qs[(r0 + i) * 68 + kk];
                acc[i][0] += qv.x * k0.x + qv.y * k0.y + qv.z * k0.z + qv.w * k0.w;
                acc[i][1] += qv.x * k1.x + qv.y * k1.y + qv.z * k1.z + qv.w * k1.w;
            }
        }
        #pragma unroll
        for (int i = 0; i < 4; ++i) {
            ss[(r0 + i) * 580 + kt * 64 + c0]     = acc[i][0] * 0.125f;
            ss[(r0 + i) * 580 + kt * 64 + c0 + 1] = acc[i][1] * 0.125f;
        }
    }
    __syncthreads();

    // ---- softmax + gated blend; 8 lanes per row ----
    {
        int r = t >> 3, c = t & 7;
        float* row = ss + r * 580;
        float mx = -1e30f;
        for (int j = 0; j < 72; ++j) mx = fmaxf(mx, row[c + 8 * j]);
        #pragma unroll
        for (int o = 4; o; o >>= 1) mx = fmaxf(mx, __shfl_xor_sync(0xFFFFFFFFu, mx, o));

        float se = 0.0f;
        for (int j = 0; j < 72; ++j) {
            int m = c + 8 * j;
            float e = expf(row[m] - mx);
            row[m] = e;
            se += e;
        }
        #pragma unroll
        for (int o = 4; o; o >>= 1) se += __shfl_xor_sync(0xFFFFFFFFu, se, o);

        float gh = gating[h];
        gh = 1.0f / (1.0f + expf(-gh));
        float pe = (1.0f - gh) / se;

        const float* pr = g_pos + ((size_t)h * Nq + n0 + r) * Nq;
        float s2 = 0.0f;
        for (int j = 0; j < 72; ++j) {
            int m = c + 8 * j;
            float a = pe * row[m] + gh * pr[m];
            row[m] = a;
            s2 += a;
        }
        #pragma unroll
        for (int o = 4; o; o >>= 1) s2 += __shfl_xor_sync(0xFFFFFFFFu, s2, o);
        if (c == 0) sinv[r] = 1.0f / s2;
    }
    __syncthreads();

    // ---- finalize: scale by row inverse-sum, write attn coalesced ----
    float* ao = dout + OFF_ATTN + (((size_t)b * Hq + h) * Nq + n0) * Nq;
    #pragma unroll 4
    for (int it = 0; it < 72; ++it) {
        int idx = t + 256 * it;            // 0 .. 18431
        int rr = idx / 576;
        int mm = idx - rr * 576;
        float val = ss[rr * 580 + mm] * sinv[rr];
        ss[rr * 580 + mm] = val;
        ao[idx] = val;
    }

    // ---- ctx = attn @ V : thread microtile = 2 rows x 4 cols ----
    int r2 = (t >> 4) * 2;
    int d0 = (t & 15) * 4;
    float c00 = 0, c01 = 0, c02 = 0, c03 = 0;
    float c10 = 0, c11 = 0, c12 = 0, c13 = 0;

    for (int kt = 0; kt < 9; ++kt) {
        __syncthreads();
        #pragma unroll
        for (int it = 0; it < 16; ++it) {
            int idx = t + 256 * it;
            int r = idx >> 6, d = idx & 63;
            kv[r * 68 + d] = vg[(size_t)kt * 4096 + idx];
        }
        __syncthreads();

        const float* rA = ss + r2 * 580 + kt * 64;
        const float* rB = ss + (r2 + 1) * 580 + kt * 64;
        #pragma unroll
        for (int ml = 0; ml < 64; ++ml) {
            float a0 = rA[ml];
            float a1 = rB[ml];
            float4 vv = *(const float4*)&kv[ml * 68 + d0];
            c00 = fmaf(a0, vv.x, c00); c01 = fmaf(a0, vv.y, c01);
            c02 = fmaf(a0, vv.z, c02); c03 = fmaf(a0, vv.w, c03);
            c10 = fmaf(a1, vv.x, c10); c11 = fmaf(a1, vv.y, c11);
            c12 = fmaf(a1, vv.z, c12); c13 = fmaf(a1, vv.w, c13);
        }
    }

    // write ctx [B,N,C] with C index = h*64 + d
    {
        size_t base0 = ((size_t)b * Nq + n0 + r2) * Cq + h * DHq + d0;
        size_t base1 = base0 + Cq;
        float4 o0 = make_float4(c00, c01, c02, c03);
        float4 o1 = make_float4(c10, c11, c12, c13);
        *(float4*)&g_ctx[base0] = o0;
        *(float4*)&g_ctx[base1] = o1;
    }
}

// ---------------------------------------------------------------------------
extern "C" void kernel_launch(void* const* d_in, const int* in_sizes, int n_in,
                              void* d_out, int out_size)
{
    const float* x      = (const float*)d_in[0];
    const float* w_qk   = (const float*)d_in[1];
    const float* w_v    = (const float*)d_in[2];
    const float* w_proj = (const float*)d_in[3];
    const float* b_proj = (const float*)d_in[4];
    const float* w_pos  = (const float*)d_in[5];
    const float* b_pos  = (const float*)d_in[6];
    const float* gating = (const float*)d_in[7];
    float* out = (float*)d_out;

    cudaFuncSetAttribute(attn_kernel, cudaFuncAttributeMaxDynamicSharedMemorySize,
                         SMEM_ATTN_BYTES);

    pos_kernel<<<dim3(Nq, Hq), 256>>>(w_pos, b_pos);
    gemm_qkv_kernel<<<dim3(18, 72), 256>>>(x, w_qk, w_v, out);
    attn_kernel<<<dim3(18, Hq, Bq), 256, SMEM_ATTN_BYTES>>>(gating, out);
    gemm_proj_kernel<<<dim3(6, 72), 256>>>(w_proj, b_proj, out);
}

// round 3
// speedup vs baseline: 3.0160x; 3.0160x over previous
#include <cuda_runtime.h>
#include <math.h>

// Problem constants
#define Bq   16
#define Nq   576
#define Cq   768
#define Hq   12
#define DHq  64
#define IMGq 24

// d_out layout (floats): out [B,N,C] | attn [B,H,N,N] | v [B,H,N,Dh]
#define OFF_ATTN 7077888
#define OFF_V    70778880

// Scratch (device globals; allocation-free rule)
__device__ float g_q[Bq * Hq * Nq * DHq];    // [B,H,N,Dh]  (tf32-rounded values)
__device__ float g_k[Bq * Hq * Nq * DHq];    // [B,H,N,Dh]
__device__ float g_ctx[Bq * Nq * Cq];        // [B,N,C] (h*64+d inner)
__device__ float g_pos[Hq * Nq * Nq];        // [H,N,N] softmaxed positional scores

// ---------------------------------------------------------------------------
// Helpers: tf32 convert + m16n8k8 tf32 mma
// ---------------------------------------------------------------------------
__device__ __forceinline__ unsigned f2tf(float f) {
    unsigned u;
    asm("cvt.rna.tf32.f32 %0, %1;" : "=r"(u) : "f"(f));
    return u;
}

__device__ __forceinline__ void mma8(float* c,
                                     unsigned a0, unsigned a1, unsigned a2, unsigned a3,
                                     unsigned b0, unsigned b1)
{
    asm volatile(
        "mma.sync.aligned.m16n8k8.row.col.f32.tf32.tf32.f32 "
        "{%0,%1,%2,%3},{%4,%5,%6,%7},{%8,%9},{%0,%1,%2,%3};\n"
        : "+f"(c[0]), "+f"(c[1]), "+f"(c[2]), "+f"(c[3])
        : "r"(a0), "r"(a1), "r"(a2), "r"(a3), "r"(b0), "r"(b1));
}

// ---------------------------------------------------------------------------
// Positional scores (unchanged): softmax over keys of analytic logits
// ---------------------------------------------------------------------------
__global__ __launch_bounds__(256) void pos_kernel(const float* __restrict__ wpos,
                                                  const float* __restrict__ bpos)
{
    int n = blockIdx.x;
    int h = blockIdx.y;
    int t = threadIdx.x;
    __shared__ float red[8];

    int nx = n % IMGq, ny = n / IMGq;
    float w0 = wpos[h], w1 = wpos[Hq + h], w2 = wpos[2 * Hq + h], bb = bpos[h];

    auto logit = [&](int m) {
        float dx = (float)(m % IMGq - nx);
        float dy = (float)(m / IMGq - ny);
        return dx * w0 + dy * w1 + (dx * dx + dy * dy) * w2 + bb;
    };

    float l0 = logit(t);
    float l1 = logit(t + 256);
    float l2 = (t < 64) ? logit(t + 512) : -1e30f;

    float mx = fmaxf(fmaxf(l0, l1), l2);
    #pragma unroll
    for (int o = 16; o; o >>= 1) mx = fmaxf(mx, __shfl_xor_sync(0xFFFFFFFFu, mx, o));
    if ((t & 31) == 0) red[t >> 5] = mx;
    __syncthreads();
    float bm = red[0];
    #pragma unroll
    for (int i = 1; i < 8; ++i) bm = fmaxf(bm, red[i]);
    __syncthreads();

    float e0 = expf(l0 - bm);
    float e1 = expf(l1 - bm);
    float e2 = (t < 64) ? expf(l2 - bm) : 0.0f;
    float s = e0 + e1 + e2;
    #pragma unroll
    for (int o = 16; o; o >>= 1) s += __shfl_xor_sync(0xFFFFFFFFu, s, o);
    if ((t & 31) == 0) red[t >> 5] = s;
    __syncthreads();
    float ts = 0.0f;
    #pragma unroll
    for (int i = 0; i < 8; ++i) ts += red[i];
    float inv = 1.0f / ts;

    float* dst = g_pos + ((size_t)h * Nq + n) * Nq;
    dst[t] = e0 * inv;
    dst[t + 256] = e1 * inv;
    if (t < 64) dst[t + 512] = e2 * inv;
}

// ---------------------------------------------------------------------------
// TF32 tensor-core GEMM: X[9216,768] @ [w_qk | w_v] -> scatter q,k -> scratch, v -> dout
// 128x128x16 block tile, 8 warps (2x4), warp tile 64x32, m16n8k8 frags
// ---------------------------------------------------------------------------
__global__ __launch_bounds__(256) void gemm_qkv_tc(const float* __restrict__ X,
                                                   const float* __restrict__ Wqk,
                                                   const float* __restrict__ Wv,
                                                   float* __restrict__ dout)
{
    __shared__ float As[16][136];   // [k][m], tf32 bit patterns
    __shared__ float Bs[16][136];   // [k][n]

    int tid = threadIdx.x;
    int lane = tid & 31, wid = tid >> 5;
    int g = lane >> 2, t = lane & 3;
    int wm = wid >> 2, wn = wid & 3;

    int row0 = blockIdx.y * 128;
    int col0 = blockIdx.x * 128;

    const float* Bp; int ldb; int cb;
    if (col0 < 1536) { Bp = Wqk; ldb = 1536; cb = col0; }
    else             { Bp = Wv;  ldb = 768;  cb = col0 - 1536; }

    float acc[4][4][4];
    #pragma unroll
    for (int i = 0; i < 4; ++i)
        #pragma unroll
        for (int j = 0; j < 4; ++j)
            #pragma unroll
            for (int r = 0; r < 4; ++r) acc[i][j][r] = 0.0f;

    for (int kt = 0; kt < 48; ++kt) {
        int k0 = kt * 16;
        // load + transpose A tile (128 x 16)
        #pragma unroll
        for (int r = 0; r < 2; ++r) {
            int i = tid + 256 * r;
            int row = i >> 2, seg = i & 3;
            float4 v = *(const float4*)(X + (size_t)(row0 + row) * Cq + k0 + seg * 4);
            As[seg * 4 + 0][row] = __uint_as_float(f2tf(v.x));
            As[seg * 4 + 1][row] = __uint_as_float(f2tf(v.y));
            As[seg * 4 + 2][row] = __uint_as_float(f2tf(v.z));
            As[seg * 4 + 3][row] = __uint_as_float(f2tf(v.w));
        }
        // load B tile (16 x 128)
        #pragma unroll
        for (int r = 0; r < 2; ++r) {
            int i = tid + 256 * r;
            int kr = i >> 5, ns = i & 31;
            float4 v = *(const float4*)(Bp + (size_t)(k0 + kr) * ldb + cb + ns * 4);
            float4 o;
            o.x = __uint_as_float(f2tf(v.x));
            o.y = __uint_as_float(f2tf(v.y));
            o.z = __uint_as_float(f2tf(v.z));
            o.w = __uint_as_float(f2tf(v.w));
            *(float4*)&Bs[kr][ns * 4] = o;
        }
        __syncthreads();

        #pragma unroll
        for (int kk = 0; kk < 16; kk += 8) {
            unsigned a[4][4], bf[4][2];
            #pragma unroll
            for (int mf = 0; mf < 4; ++mf) {
                int m = wm * 64 + mf * 16;
                a[mf][0] = __float_as_uint(As[kk + t    ][m + g    ]);
                a[mf][1] = __float_as_uint(As[kk + t    ][m + g + 8]);
                a[mf][2] = __float_as_uint(As[kk + t + 4][m + g    ]);
                a[mf][3] = __float_as_uint(As[kk + t + 4][m + g + 8]);
            }
            #pragma unroll
            for (int nf = 0; nf < 4; ++nf) {
                int n = wn * 32 + nf * 8;
                bf[nf][0] = __float_as_uint(Bs[kk + t    ][n + g]);
                bf[nf][1] = __float_as_uint(Bs[kk + t + 4][n + g]);
            }
            #pragma unroll
            for (int mf = 0; mf < 4; ++mf)
                #pragma unroll
                for (int nf = 0; nf < 4; ++nf)
                    mma8(acc[mf][nf], a[mf][0], a[mf][1], a[mf][2], a[mf][3],
                         bf[nf][0], bf[nf][1]);
        }
        __syncthreads();
    }

    // scatter epilogue
    #pragma unroll
    for (int mf = 0; mf < 4; ++mf) {
        #pragma unroll
        for (int ri = 0; ri < 4; ++ri) {
            int gm = row0 + wm * 64 + mf * 16 + g + ((ri >> 1) ? 8 : 0);
            int bi = gm / Nq;
            int n  = gm - bi * Nq;
            #pragma unroll
            for (int nf = 0; nf < 4; ++nf) {
                int gn = col0 + wn * 32 + nf * 8 + 2 * t + (ri & 1);
                float val = acc[mf][nf][ri];
                if (gn < 768) {
                    int h = gn >> 6, d = gn & 63;
                    g_q[(((size_t)bi * Hq + h) * Nq + n) * DHq + d] = val;
                } else if (gn < 1536) {
                    int rr = gn - 768; int h = rr >> 6, d = rr & 63;
                    g_k[(((size_t)bi * Hq + h) * Nq + n) * DHq + d] = val;
                } else {
                    int rr = gn - 1536; int h = rr >> 6, d = rr & 63;
                    dout[OFF_V + (((size_t)bi * Hq + h) * Nq + n) * DHq + d] = val;
                }
            }
        }
    }
}

// ---------------------------------------------------------------------------
// Projection GEMM (tf32 TC): g_ctx [9216 x 768] @ w_proj + b_proj -> dout[0..]
// ---------------------------------------------------------------------------
__global__ __launch_bounds__(256) void gemm_proj_tc(const float* __restrict__ Wp,
                                                    const float* __restrict__ bp,
                                                    float* __restrict__ dout)
{
    __shared__ float As[16][136];
    __shared__ float Bs[16][136];

    int tid = threadIdx.x;
    int lane = tid & 31, wid = tid >> 5;
    int g = lane >> 2, t = lane & 3;
    int wm = wid >> 2, wn = wid & 3;

    int row0 = blockIdx.y * 128;
    int col0 = blockIdx.x * 128;

    float acc[4][4][4];
    #pragma unroll
    for (int i = 0; i < 4; ++i)
        #pragma unroll
        for (int j = 0; j < 4; ++j)
            #pragma unroll
            for (int r = 0; r < 4; ++r) acc[i][j][r] = 0.0f;

    for (int kt = 0; kt < 48; ++kt) {
        int k0 = kt * 16;
        #pragma unroll
        for (int r = 0; r < 2; ++r) {
            int i = tid + 256 * r;
            int row = i >> 2, seg = i & 3;
            float4 v = *(const float4*)(g_ctx + (size_t)(row0 + row) * Cq + k0 + seg * 4);
            As[seg * 4 + 0][row] = __uint_as_float(f2tf(v.x));
            As[seg * 4 + 1][row] = __uint_as_float(f2tf(v.y));
            As[seg * 4 + 2][row] = __uint_as_float(f2tf(v.z));
            As[seg * 4 + 3][row] = __uint_as_float(f2tf(v.w));
        }
        #pragma unroll
        for (int r = 0; r < 2; ++r) {
            int i = tid + 256 * r;
            int kr = i >> 5, ns = i & 31;
            float4 v = *(const float4*)(Wp + (size_t)(k0 + kr) * Cq + col0 + ns * 4);
            float4 o;
            o.x = __uint_as_float(f2tf(v.x));
            o.y = __uint_as_float(f2tf(v.y));
            o.z = __uint_as_float(f2tf(v.z));
            o.w = __uint_as_float(f2tf(v.w));
            *(float4*)&Bs[kr][ns * 4] = o;
        }
        __syncthreads();

        #pragma unroll
        for (int kk = 0; kk < 16; kk += 8) {
            unsigned a[4][4], bf[4][2];
            #pragma unroll
            for (int mf = 0; mf < 4; ++mf) {
                int m = wm * 64 + mf * 16;
                a[mf][0] = __float_as_uint(As[kk + t    ][m + g    ]);
                a[mf][1] = __float_as_uint(As[kk + t    ][m + g + 8]);
                a[mf][2] = __float_as_uint(As[kk + t + 4][m + g    ]);
                a[mf][3] = __float_as_uint(As[kk + t + 4][m + g + 8]);
            }
            #pragma unroll
            for (int nf = 0; nf < 4; ++nf) {
                int n = wn * 32 + nf * 8;
                bf[nf][0] = __float_as_uint(Bs[kk + t    ][n + g]);
                bf[nf][1] = __float_as_uint(Bs[kk + t + 4][n + g]);
            }
            #pragma unroll
            for (int mf = 0; mf < 4; ++mf)
                #pragma unroll
                for (int nf = 0; nf < 4; ++nf)
                    mma8(acc[mf][nf], a[mf][0], a[mf][1], a[mf][2], a[mf][3],
                         bf[nf][0], bf[nf][1]);
        }
        __syncthreads();
    }

    #pragma unroll
    for (int mf = 0; mf < 4; ++mf) {
        #pragma unroll
        for (int ri = 0; ri < 4; ++ri) {
            int gm = row0 + wm * 64 + mf * 16 + g + ((ri >> 1) ? 8 : 0);
            #pragma unroll
            for (int nf = 0; nf < 4; ++nf) {
                int gn = col0 + wn * 32 + nf * 8 + 2 * t + (ri & 1);
                dout[(size_t)gm * Cq + gn] = acc[mf][nf][ri] + bp[gn];
            }
        }
    }
}

// ---------------------------------------------------------------------------
// Fused attention with tf32 TC for QK^T and P@V. Per block: (32 queries, h, b).
// smem: qs[32][68] + kv[64][68] + ss[32][580] = 100,352 bytes
// ---------------------------------------------------------------------------
#define SMEM_ATTN_BYTES ((32 * 68 + 64 * 68 + 32 * 580) * 4)

__global__ __launch_bounds__(256) void attn_tc(const float* __restrict__ gating,
                                               float* __restrict__ dout)
{
    extern __shared__ float sm[];
    float* qs = sm;                       // 32 x 68 (tf32)
    float* kv = sm + 32 * 68;             // 64 x 68 (tf32)
    float* ss = sm + 32 * 68 + 64 * 68;   // 32 x 580 (fp32 scores/probs)
    __shared__ float sinv[32];

    int tid = threadIdx.x;
    int lane = tid & 31, w = tid >> 5;
    int g = lane >> 2, t = lane & 3;
    int qt = blockIdx.x;    // 0..17
    int h  = blockIdx.y;
    int b  = blockIdx.z;
    int n0 = qt * 32;

    const float* qg = g_q + (((size_t)b * Hq + h) * Nq + n0) * DHq;
    const float* kg = g_k + (((size_t)b * Hq + h) * Nq) * DHq;
    const float* vg = dout + OFF_V + (((size_t)b * Hq + h) * Nq) * DHq;

    // load Q tile (32x64) with tf32 rounding
    #pragma unroll
    for (int it = 0; it < 8; ++it) {
        int idx = tid + 256 * it;
        int r = idx >> 6, d = idx & 63;
        qs[r * 68 + d] = __uint_as_float(f2tf(qg[idx]));
    }

    // ---- scores: per 64-key chunk, warp w owns keys [w*8, w*8+8) ----
    for (int kt = 0; kt < 9; ++kt) {
        __syncthreads();
        #pragma unroll
        for (int it = 0; it < 16; ++it) {
            int idx = tid + 256 * it;
            int r = idx >> 6, d = idx & 63;
            kv[r * 68 + d] = __uint_as_float(f2tf(kg[(size_t)kt * 4096 + idx]));
        }
        __syncthreads();

        float c0[4] = {0.f, 0.f, 0.f, 0.f};
        float c1[4] = {0.f, 0.f, 0.f, 0.f};
        #pragma unroll
        for (int kk = 0; kk < 64; kk += 8) {
            unsigned b0 = __float_as_uint(kv[(w * 8 + g) * 68 + kk + t]);
            unsigned b1 = __float_as_uint(kv[(w * 8 + g) * 68 + kk + t + 4]);
            unsigned a0 = __float_as_uint(qs[(g     ) * 68 + kk + t]);
            unsigned a1 = __float_as_uint(qs[(g +  8) * 68 + kk + t]);
            unsigned a2 = __float_as_uint(qs[(g     ) * 68 + kk + t + 4]);
            unsigned a3 = __float_as_uint(qs[(g +  8) * 68 + kk + t + 4]);
            mma8(c0, a0, a1, a2, a3, b0, b1);
            a0 = __float_as_uint(qs[(g + 16) * 68 + kk + t]);
            a1 = __float_as_uint(qs[(g + 24) * 68 + kk + t]);
            a2 = __float_as_uint(qs[(g + 16) * 68 + kk + t + 4]);
            a3 = __float_as_uint(qs[(g + 24) * 68 + kk + t + 4]);
            mma8(c1, a0, a1, a2, a3, b0, b1);
        }
        int colb = kt * 64 + w * 8 + 2 * t;
        ss[(g     ) * 580 + colb    ] = c0[0] * 0.125f;
        ss[(g     ) * 580 + colb + 1] = c0[1] * 0.125f;
        ss[(g +  8) * 580 + colb    ] = c0[2] * 0.125f;
        ss[(g +  8) * 580 + colb + 1] = c0[3] * 0.125f;
        ss[(g + 16) * 580 + colb    ] = c1[0] * 0.125f;
        ss[(g + 16) * 580 + colb + 1] = c1[1] * 0.125f;
        ss[(g + 24) * 580 + colb    ] = c1[2] * 0.125f;
        ss[(g + 24) * 580 + colb + 1] = c1[3] * 0.125f;
    }
    __syncthreads();

    // ---- softmax + gated blend; 8 lanes per row ----
    {
        int r = tid >> 3, c = tid & 7;
        float* row = ss + r * 580;
        float mx = -1e30f;
        for (int j = 0; j < 72; ++j) mx = fmaxf(mx, row[c + 8 * j]);
        #pragma unroll
        for (int o = 4; o; o >>= 1) mx = fmaxf(mx, __shfl_xor_sync(0xFFFFFFFFu, mx, o));

        float se = 0.0f;
        for (int j = 0; j < 72; ++j) {
            int m = c + 8 * j;
            float e = expf(row[m] - mx);
            row[m] = e;
            se += e;
        }
        #pragma unroll
        for (int o = 4; o; o >>= 1) se += __shfl_xor_sync(0xFFFFFFFFu, se, o);

        float gh = gating[h];
        gh = 1.0f / (1.0f + expf(-gh));
        float pe = (1.0f - gh) / se;

        const float* pr = g_pos + ((size_t)h * Nq + n0 + r) * Nq;
        float s2 = 0.0f;
        for (int j = 0; j < 72; ++j) {
            int m = c + 8 * j;
            float a = pe * row[m] + gh * pr[m];
            row[m] = a;
            s2 += a;
        }
        #pragma unroll
        for (int o = 4; o; o >>= 1) s2 += __shfl_xor_sync(0xFFFFFFFFu, s2, o);
        if (c == 0) sinv[r] = 1.0f / s2;
    }
    __syncthreads();

    // ---- finalize: scale by row inverse-sum, write attn coalesced ----
    float* ao = dout + OFF_ATTN + (((size_t)b * Hq + h) * Nq + n0) * Nq;
    #pragma unroll 4
    for (int it = 0; it < 72; ++it) {
        int idx = tid + 256 * it;
        int rr = idx / 576;
        int mm = idx - rr * 576;
        float val = ss[rr * 580 + mm] * sinv[rr];
        ss[rr * 580 + mm] = val;
        ao[idx] = val;
    }

    // ---- ctx = P @ V ; warp w owns d-cols [w*8, w*8+8) ----
    float p0[4] = {0.f, 0.f, 0.f, 0.f};
    float p1[4] = {0.f, 0.f, 0.f, 0.f};
    for (int kt = 0; kt < 9; ++kt) {
        __syncthreads();
        #pragma unroll
        for (int it = 0; it < 16; ++it) {
            int idx = tid + 256 * it;
            int r = idx >> 6, d = idx & 63;
            kv[r * 68 + d] = __uint_as_float(f2tf(vg[(size_t)kt * 4096 + idx]));
        }
        __syncthreads();

        #pragma unroll
        for (int kk = 0; kk < 64; kk += 8) {
            unsigned b0 = __float_as_uint(kv[(kk + t    ) * 68 + w * 8 + g]);
            unsigned b1 = __float_as_uint(kv[(kk + t + 4) * 68 + w * 8 + g]);
            int cb = kt * 64 + kk;
            unsigned a0 = f2tf(ss[(g     ) * 580 + cb + t]);
            unsigned a1 = f2tf(ss[(g +  8) * 580 + cb + t]);
            unsigned a2 = f2tf(ss[(g     ) * 580 + cb + t + 4]);
            unsigned a3 = f2tf(ss[(g +  8) * 580 + cb + t + 4]);
            mma8(p0, a0, a1, a2, a3, b0, b1);
            a0 = f2tf(ss[(g + 16) * 580 + cb + t]);
            a1 = f2tf(ss[(g + 24) * 580 + cb + t]);
            a2 = f2tf(ss[(g + 16) * 580 + cb + t + 4]);
            a3 = f2tf(ss[(g + 24) * 580 + cb + t + 4]);
            mma8(p1, a0, a1, a2, a3, b0, b1);
        }
    }

    // write ctx [B,N,C] with C index = h*64 + d
    {
        size_t bn = (size_t)b * Nq + n0;
        int d0 = w * 8 + 2 * t;
        size_t hofs = (size_t)h * DHq;
        g_ctx[(bn + g     ) * Cq + hofs + d0    ] = p0[0];
        g_ctx[(bn + g     ) * Cq + hofs + d0 + 1] = p0[1];
        g_ctx[(bn + g +  8) * Cq + hofs + d0    ] = p0[2];
        g_ctx[(bn + g +  8) * Cq + hofs + d0 + 1] = p0[3];
        g_ctx[(bn + g + 16) * Cq + hofs + d0    ] = p1[0];
        g_ctx[(bn + g + 16) * Cq + hofs + d0 + 1] = p1[1];
        g_ctx[(bn + g + 24) * Cq + hofs + d0    ] = p1[2];
        g_ctx[(bn + g + 24) * Cq + hofs + d0 + 1] = p1[3];
    }
}

// ---------------------------------------------------------------------------
extern "C" void kernel_launch(void* const* d_in, const int* in_sizes, int n_in,
                              void* d_out, int out_size)
{
    const float* x      = (const float*)d_in[0];
    const float* w_qk   = (const float*)d_in[1];
    const float* w_v    = (const float*)d_in[2];
    const float* w_proj = (const float*)d_in[3];
    const float* b_proj = (const float*)d_in[4];
    const float* w_pos  = (const float*)d_in[5];
    const float* b_pos  = (const float*)d_in[6];
    const float* gating = (const float*)d_in[7];
    float* out = (float*)d_out;

    cudaFuncSetAttribute(attn_tc, cudaFuncAttributeMaxDynamicSharedMemorySize,
                         SMEM_ATTN_BYTES);

    pos_kernel<<<dim3(Nq, Hq), 256>>>(w_pos, b_pos);
    gemm_qkv_tc<<<dim3(18, 72), 256>>>(x, w_qk, w_v, out);
    attn_tc<<<dim3(18, Hq, Bq), 256, SMEM_ATTN_BYTES>>>(gating, out);
    gemm_proj_tc<<<dim3(6, 72), 256>>>(w_proj, b_proj, out);
}

// round 4
// speedup vs baseline: 3.6649x; 1.2151x over previous
#include <cuda_runtime.h>
#include <math.h>

// Problem constants
#define Bq   16
#define Nq   576
#define Cq   768
#define Hq   12
#define DHq  64
#define IMGq 24

// d_out layout (floats): out [B,N,C] | attn [B,H,N,N] | v [B,H,N,Dh]
#define OFF_ATTN 7077888
#define OFF_V    70778880

// Scratch (device globals; allocation-free rule). All *_t hold tf32-rounded fp32.
__device__ float g_xt[Bq * Nq * Cq];          // tf32(x)
__device__ float g_wqkt[Cq * 2 * Cq];         // tf32(w_qk)
__device__ float g_wvt[Cq * Cq];              // tf32(w_v)
__device__ float g_wpt[Cq * Cq];              // tf32(w_proj)
__device__ float g_q[Bq * Hq * Nq * DHq];     // tf32(q)  [B,H,N,Dh]
__device__ float g_k[Bq * Hq * Nq * DHq];     // tf32(k)
__device__ float g_vt[Bq * Hq * Nq * DHq];    // tf32(v)  (exact v goes to d_out)
__device__ float g_ctx[Bq * Nq * Cq];         // tf32(ctx) [B,N,C]
__device__ float g_pos[Hq * Nq * Nq];         // fp32 positional probs [H,N,N]

// ---------------------------------------------------------------------------
__device__ __forceinline__ unsigned f2tf(float f) {
    unsigned u;
    asm("cvt.rna.tf32.f32 %0, %1;" : "=r"(u) : "f"(f));
    return u;
}
__device__ __forceinline__ float f2tff(float f) {
    return __uint_as_float(f2tf(f));
}

__device__ __forceinline__ void mma8(float* c,
                                     unsigned a0, unsigned a1, unsigned a2, unsigned a3,
                                     unsigned b0, unsigned b1)
{
    asm volatile(
        "mma.sync.aligned.m16n8k8.row.col.f32.tf32.tf32.f32 "
        "{%0,%1,%2,%3},{%4,%5,%6,%7},{%8,%9},{%0,%1,%2,%3};\n"
        : "+f"(c[0]), "+f"(c[1]), "+f"(c[2]), "+f"(c[3])
        : "r"(a0), "r"(a1), "r"(a2), "r"(a3), "r"(b0), "r"(b1));
}

__device__ __forceinline__ void cpasync16(void* smem_dst, const void* gmem_src) {
    unsigned s = (unsigned)__cvta_generic_to_shared(smem_dst);
    asm volatile("cp.async.cg.shared.global [%0], [%1], 16;\n" :: "r"(s), "l"(gmem_src));
}
#define CP_COMMIT() asm volatile("cp.async.commit_group;\n" ::: "memory")
#define CP_WAIT1()  asm volatile("cp.async.wait_group 1;\n" ::: "memory")
#define CP_WAIT0()  asm volatile("cp.async.wait_group 0;\n" ::: "memory")

// ---------------------------------------------------------------------------
// Elementwise tf32 rounding pre-pass (float4)
// ---------------------------------------------------------------------------
__global__ __launch_bounds__(256) void cvt_kernel(const float* __restrict__ src,
                                                  float* __restrict__ dst, int n4)
{
    int i = blockIdx.x * 256 + threadIdx.x;
    if (i < n4) {
        float4 v = ((const float4*)src)[i];
        float4 o;
        o.x = f2tff(v.x); o.y = f2tff(v.y); o.z = f2tff(v.z); o.w = f2tff(v.w);
        ((float4*)dst)[i] = o;
    }
}

// ---------------------------------------------------------------------------
// Positional scores: softmax over keys of analytic logits
// ---------------------------------------------------------------------------
__global__ __launch_bounds__(256) void pos_kernel(const float* __restrict__ wpos,
                                                  const float* __restrict__ bpos)
{
    int n = blockIdx.x;
    int h = blockIdx.y;
    int t = threadIdx.x;
    __shared__ float red[8];

    int nx = n % IMGq, ny = n / IMGq;
    float w0 = wpos[h], w1 = wpos[Hq + h], w2 = wpos[2 * Hq + h], bb = bpos[h];

    auto logit = [&](int m) {
        float dx = (float)(m % IMGq - nx);
        float dy = (float)(m / IMGq - ny);
        return dx * w0 + dy * w1 + (dx * dx + dy * dy) * w2 + bb;
    };

    float l0 = logit(t);
    float l1 = logit(t + 256);
    float l2 = (t < 64) ? logit(t + 512) : -1e30f;

    float mx = fmaxf(fmaxf(l0, l1), l2);
    #pragma unroll
    for (int o = 16; o; o >>= 1) mx = fmaxf(mx, __shfl_xor_sync(0xFFFFFFFFu, mx, o));
    if ((t & 31) == 0) red[t >> 5] = mx;
    __syncthreads();
    float bm = red[0];
    #pragma unroll
    for (int i = 1; i < 8; ++i) bm = fmaxf(bm, red[i]);
    __syncthreads();

    float e0 = expf(l0 - bm);
    float e1 = expf(l1 - bm);
    float e2 = (t < 64) ? expf(l2 - bm) : 0.0f;
    float s = e0 + e1 + e2;
    #pragma unroll
    for (int o = 16; o; o >>= 1) s += __shfl_xor_sync(0xFFFFFFFFu, s, o);
    if ((t & 31) == 0) red[t >> 5] = s;
    __syncthreads();
    float ts = 0.0f;
    #pragma unroll
    for (int i = 0; i < 8; ++i) ts += red[i];
    float inv = 1.0f / ts;

    float* dst = g_pos + ((size_t)h * Nq + n) * Nq;
    dst[t] = e0 * inv;
    dst[t + 256] = e1 * inv;
    if (t < 64) dst[t + 512] = e2 * inv;
}

// ---------------------------------------------------------------------------
// Pipelined TF32 GEMM: g_xt[9216,768] @ [g_wqkt | g_wvt] -> q,k scratch, v -> dout
// 128x128x16 block tile, cp.async 2-stage, A smem [m][k] ld=20, B smem [k][n] ld=136
// ---------------------------------------------------------------------------
#define LDA 20
#define LDB 136

__global__ __launch_bounds__(256, 2) void gemm_qkv_tc(float* __restrict__ dout)
{
    __shared__ float As[2][128 * LDA];
    __shared__ float Bs[2][16 * LDB];

    int tid = threadIdx.x;
    int lane = tid & 31, wid = tid >> 5;
    int g = lane >> 2, t = lane & 3;
    int wm = wid >> 2, wn = wid & 3;

    int row0 = blockIdx.y * 128;
    int col0 = blockIdx.x * 128;

    const float* Bp; int ldb; int cb;
    if (col0 < 1536) { Bp = g_wqkt; ldb = 1536; cb = col0; }
    else             { Bp = g_wvt;  ldb = 768;  cb = col0 - 1536; }

    float acc[4][4][4];
    #pragma unroll
    for (int i = 0; i < 4; ++i)
        #pragma unroll
        for (int j = 0; j < 4; ++j)
            #pragma unroll
            for (int r = 0; r < 4; ++r) acc[i][j][r] = 0.0f;

    auto issue = [&](int kt, int s) {
        int k0 = kt * 16;
        #pragma unroll
        for (int r = 0; r < 2; ++r) {
            int c = tid + 256 * r;
            int row = c >> 2, seg = c & 3;
            cpasync16(&As[s][row * LDA + seg * 4],
                      g_xt + (size_t)(row0 + row) * Cq + k0 + seg * 4);
        }
        #pragma unroll
        for (int r = 0; r < 2; ++r) {
            int c = tid + 256 * r;
            int kr = c >> 5, ns = c & 31;
            cpasync16(&Bs[s][kr * LDB + ns * 4],
                      Bp + (size_t)(k0 + kr) * ldb + cb + ns * 4);
        }
        CP_COMMIT();
    };

    issue(0, 0);
    for (int kt = 0; kt < 48; ++kt) {
        __syncthreads();
        if (kt + 1 < 48) { issue(kt + 1, (kt + 1) & 1); CP_WAIT1(); }
        else             { CP_WAIT0(); }
        __syncthreads();

        const float* A = As[kt & 1];
        const float* B = Bs[kt & 1];
        #pragma unroll
        for (int kk = 0; kk < 16; kk += 8) {
            unsigned a[4][4], bf[4][2];
            #pragma unroll
            for (int mf = 0; mf < 4; ++mf) {
                int m = wm * 64 + mf * 16;
                a[mf][0] = __float_as_uint(A[(m + g    ) * LDA + kk + t    ]);
                a[mf][1] = __float_as_uint(A[(m + g + 8) * LDA + kk + t    ]);
                a[mf][2] = __float_as_uint(A[(m + g    ) * LDA + kk + t + 4]);
                a[mf][3] = __float_as_uint(A[(m + g + 8) * LDA + kk + t + 4]);
            }
            #pragma unroll
            for (int nf = 0; nf < 4; ++nf) {
                int n = wn * 32 + nf * 8;
                bf[nf][0] = __float_as_uint(B[(kk + t    ) * LDB + n + g]);
                bf[nf][1] = __float_as_uint(B[(kk + t + 4) * LDB + n + g]);
            }
            #pragma unroll
            for (int mf = 0; mf < 4; ++mf)
                #pragma unroll
                for (int nf = 0; nf < 4; ++nf)
                    mma8(acc[mf][nf], a[mf][0], a[mf][1], a[mf][2], a[mf][3],
                         bf[nf][0], bf[nf][1]);
        }
    }

    // scatter epilogue (q,k tf32-rounded; v exact -> dout, tf32 -> g_vt)
    #pragma unroll
    for (int mf = 0; mf < 4; ++mf) {
        #pragma unroll
        for (int ri = 0; ri < 4; ++ri) {
            int gm = row0 + wm * 64 + mf * 16 + g + ((ri >> 1) ? 8 : 0);
            int bi = gm / Nq;
            int n  = gm - bi * Nq;
            #pragma unroll
            for (int nf = 0; nf < 4; ++nf) {
                int gn = col0 + wn * 32 + nf * 8 + 2 * t + (ri & 1);
                float val = acc[mf][nf][ri];
                if (gn < 768) {
                    int h = gn >> 6, d = gn & 63;
                    g_q[(((size_t)bi * Hq + h) * Nq + n) * DHq + d] = f2tff(val);
                } else if (gn < 1536) {
                    int rr = gn - 768; int h = rr >> 6, d = rr & 63;
                    g_k[(((size_t)bi * Hq + h) * Nq + n) * DHq + d] = f2tff(val);
                } else {
                    int rr = gn - 1536; int h = rr >> 6, d = rr & 63;
                    size_t o = (((size_t)bi * Hq + h) * Nq + n) * DHq + d;
                    dout[OFF_V + o] = val;
                    g_vt[o] = f2tff(val);
                }
            }
        }
    }
}

// ---------------------------------------------------------------------------
// Pipelined projection GEMM: g_ctx [9216 x 768] @ g_wpt + b_proj -> dout[0..]
// ---------------------------------------------------------------------------
__global__ __launch_bounds__(256, 2) void gemm_proj_tc(const float* __restrict__ bp,
                                                       float* __restrict__ dout)
{
    __shared__ float As[2][128 * LDA];
    __shared__ float Bs[2][16 * LDB];

    int tid = threadIdx.x;
    int lane = tid & 31, wid = tid >> 5;
    int g = lane >> 2, t = lane & 3;
    int wm = wid >> 2, wn = wid & 3;

    int row0 = blockIdx.y * 128;
    int col0 = blockIdx.x * 128;

    float acc[4][4][4];
    #pragma unroll
    for (int i = 0; i < 4; ++i)
        #pragma unroll
        for (int j = 0; j < 4; ++j)
            #pragma unroll
            for (int r = 0; r < 4; ++r) acc[i][j][r] = 0.0f;

    auto issue = [&](int kt, int s) {
        int k0 = kt * 16;
        #pragma unroll
        for (int r = 0; r < 2; ++r) {
            int c = tid + 256 * r;
            int row = c >> 2, seg = c & 3;
            cpasync16(&As[s][row * LDA + seg * 4],
                      g_ctx + (size_t)(row0 + row) * Cq + k0 + seg * 4);
        }
        #pragma unroll
        for (int r = 0; r < 2; ++r) {
            int c = tid + 256 * r;
            int kr = c >> 5, ns = c & 31;
            cpasync16(&Bs[s][kr * LDB + ns * 4],
                      g_wpt + (size_t)(k0 + kr) * Cq + col0 + ns * 4);
        }
        CP_COMMIT();
    };

    issue(0, 0);
    for (int kt = 0; kt < 48; ++kt) {
        __syncthreads();
        if (kt + 1 < 48) { issue(kt + 1, (kt + 1) & 1); CP_WAIT1(); }
        else             { CP_WAIT0(); }
        __syncthreads();

        const float* A = As[kt & 1];
        const float* B = Bs[kt & 1];
        #pragma unroll
        for (int kk = 0; kk < 16; kk += 8) {
            unsigned a[4][4], bf[4][2];
            #pragma unroll
            for (int mf = 0; mf < 4; ++mf) {
                int m = wm * 64 + mf * 16;
                a[mf][0] = __float_as_uint(A[(m + g    ) * LDA + kk + t    ]);
                a[mf][1] = __float_as_uint(A[(m + g + 8) * LDA + kk + t    ]);
                a[mf][2] = __float_as_uint(A[(m + g    ) * LDA + kk + t + 4]);
                a[mf][3] = __float_as_uint(A[(m + g + 8) * LDA + kk + t + 4]);
            }
            #pragma unroll
            for (int nf = 0; nf < 4; ++nf) {
                int n = wn * 32 + nf * 8;
                bf[nf][0] = __float_as_uint(B[(kk + t    ) * LDB + n + g]);
                bf[nf][1] = __float_as_uint(B[(kk + t + 4) * LDB + n + g]);
            }
            #pragma unroll
            for (int mf = 0; mf < 4; ++mf)
                #pragma unroll
                for (int nf = 0; nf < 4; ++nf)
                    mma8(acc[mf][nf], a[mf][0], a[mf][1], a[mf][2], a[mf][3],
                         bf[nf][0], bf[nf][1]);
        }
    }

    #pragma unroll
    for (int mf = 0; mf < 4; ++mf) {
        #pragma unroll
        for (int ri = 0; ri < 4; ++ri) {
            int gm = row0 + wm * 64 + mf * 16 + g + ((ri >> 1) ? 8 : 0);
            #pragma unroll
            for (int nf = 0; nf < 4; ++nf) {
                int gn = col0 + wn * 32 + nf * 8 + 2 * t + (ri & 1);
                dout[(size_t)gm * Cq + gn] = acc[mf][nf][ri] + bp[gn];
            }
        }
    }
}

// ---------------------------------------------------------------------------
// Fused attention, tf32 TC, cp.async double-buffered K/V chunks.
// smem: qs[32*68] + kv[2][64*72] + ss[32*580] = 119,808 bytes (dynamic)
// ---------------------------------------------------------------------------
#define LDKV 72
#define SMEM_ATTN_BYTES ((32 * 68 + 2 * 64 * LDKV + 32 * 580) * 4)

__global__ __launch_bounds__(256) void attn_tc(const float* __restrict__ gating,
                                               float* __restrict__ dout)
{
    extern __shared__ float sm[];
    float* qs  = sm;                              // 32 x 68 (tf32)
    float* kvb = sm + 32 * 68;                    // 2 x 64 x 72 (tf32)
    float* ss  = sm + 32 * 68 + 2 * 64 * LDKV;    // 32 x 580
    __shared__ float sinv[32];

    int tid = threadIdx.x;
    int lane = tid & 31, w = tid >> 5;
    int g = lane >> 2, t = lane & 3;
    int qt = blockIdx.x;
    int h  = blockIdx.y;
    int b  = blockIdx.z;
    int n0 = qt * 32;

    const float* qg = g_q  + (((size_t)b * Hq + h) * Nq + n0) * DHq;
    const float* kg = g_k  + (((size_t)b * Hq + h) * Nq) * DHq;
    const float* vg = g_vt + (((size_t)b * Hq + h) * Nq) * DHq;

    auto issueKV = [&](const float* src, int kt, int s) {
        float* dst = kvb + s * (64 * LDKV);
        #pragma unroll
        for (int i = 0; i < 4; ++i) {
            int c = tid + 256 * i;
            int row = c >> 4, sg = c & 15;
            cpasync16(&dst[row * LDKV + sg * 4],
                      src + (size_t)kt * 4096 + row * 64 + sg * 4);
        }
        CP_COMMIT();
    };

    // load Q tile (already tf32)
    #pragma unroll
    for (int it = 0; it < 8; ++it) {
        int idx = tid + 256 * it;
        int r = idx >> 6, d = idx & 63;
        qs[r * 68 + d] = qg[idx];
    }

    // ---- scores ----
    issueKV(kg, 0, 0);
    for (int kt = 0; kt < 9; ++kt) {
        __syncthreads();
        if (kt + 1 < 9) { issueKV(kg, kt + 1, (kt + 1) & 1); CP_WAIT1(); }
        else            { CP_WAIT0(); }
        __syncthreads();
        const float* kv = kvb + (kt & 1) * (64 * LDKV);

        float c0[4] = {0.f, 0.f, 0.f, 0.f};
        float c1[4] = {0.f, 0.f, 0.f, 0.f};
        #pragma unroll
        for (int kk = 0; kk < 64; kk += 8) {
            unsigned b0 = __float_as_uint(kv[(w * 8 + g) * LDKV + kk + t]);
            unsigned b1 = __float_as_uint(kv[(w * 8 + g) * LDKV + kk + t + 4]);
            unsigned a0 = __float_as_uint(qs[(g     ) * 68 + kk + t]);
            unsigned a1 = __float_as_uint(qs[(g +  8) * 68 + kk + t]);
            unsigned a2 = __float_as_uint(qs[(g     ) * 68 + kk + t + 4]);
            unsigned a3 = __float_as_uint(qs[(g +  8) * 68 + kk + t + 4]);
            mma8(c0, a0, a1, a2, a3, b0, b1);
            a0 = __float_as_uint(qs[(g + 16) * 68 + kk + t]);
            a1 = __float_as_uint(qs[(g + 24) * 68 + kk + t]);
            a2 = __float_as_uint(qs[(g + 16) * 68 + kk + t + 4]);
            a3 = __float_as_uint(qs[(g + 24) * 68 + kk + t + 4]);
            mma8(c1, a0, a1, a2, a3, b0, b1);
        }
        int colb = kt * 64 + w * 8 + 2 * t;
        ss[(g     ) * 580 + colb    ] = c0[0] * 0.125f;
        ss[(g     ) * 580 + colb + 1] = c0[1] * 0.125f;
        ss[(g +  8) * 580 + colb    ] = c0[2] * 0.125f;
        ss[(g +  8) * 580 + colb + 1] = c0[3] * 0.125f;
        ss[(g + 16) * 580 + colb    ] = c1[0] * 0.125f;
        ss[(g + 16) * 580 + colb + 1] = c1[1] * 0.125f;
        ss[(g + 24) * 580 + colb    ] = c1[2] * 0.125f;
        ss[(g + 24) * 580 + colb + 1] = c1[3] * 0.125f;
    }
    __syncthreads();

    // ---- softmax + gated blend; 8 lanes per row ----
    {
        int r = tid >> 3, c = tid & 7;
        float* row = ss + r * 580;
        float mx = -1e30f;
        for (int j = 0; j < 72; ++j) mx = fmaxf(mx, row[c + 8 * j]);
        #pragma unroll
        for (int o = 4; o; o >>= 1) mx = fmaxf(mx, __shfl_xor_sync(0xFFFFFFFFu, mx, o));

        float se = 0.0f;
        for (int j = 0; j < 72; ++j) {
            int m = c + 8 * j;
            float e = expf(row[m] - mx);
            row[m] = e;
            se += e;
        }
        #pragma unroll
        for (int o = 4; o; o >>= 1) se += __shfl_xor_sync(0xFFFFFFFFu, se, o);

        float gh = gating[h];
        gh = 1.0f / (1.0f + expf(-gh));
        float pe = (1.0f - gh) / se;

        const float* pr = g_pos + ((size_t)h * Nq + n0 + r) * Nq;
        float s2 = 0.0f;
        for (int j = 0; j < 72; ++j) {
            int m = c + 8 * j;
            float a = pe * row[m] + gh * pr[m];
            row[m] = a;
            s2 += a;
        }
        #pragma unroll
        for (int o = 4; o; o >>= 1) s2 += __shfl_xor_sync(0xFFFFFFFFu, s2, o);
        if (c == 0) sinv[r] = 1.0f / s2;
    }
    __syncthreads();

    // ---- finalize: write exact attn to dout; keep tf32-rounded probs in ss ----
    float* ao = dout + OFF_ATTN + (((size_t)b * Hq + h) * Nq + n0) * Nq;
    #pragma unroll 4
    for (int it = 0; it < 72; ++it) {
        int idx = tid + 256 * it;
        int rr = idx / 576;
        int mm = idx - rr * 576;
        float val = ss[rr * 580 + mm] * sinv[rr];
        ao[idx] = val;
        ss[rr * 580 + mm] = f2tff(val);
    }

    // ---- ctx = P @ V ; warp w owns d-cols [w*8, w*8+8) ----
    float p0[4] = {0.f, 0.f, 0.f, 0.f};
    float p1[4] = {0.f, 0.f, 0.f, 0.f};
    issueKV(vg, 0, 0);
    for (int kt = 0; kt < 9; ++kt) {
        __syncthreads();
        if (kt + 1 < 9) { issueKV(vg, kt + 1, (kt + 1) & 1); CP_WAIT1(); }
        else            { CP_WAIT0(); }
        __syncthreads();
        const float* kv = kvb + (kt & 1) * (64 * LDKV);

        #pragma unroll
        for (int kk = 0; kk < 64; kk += 8) {
            unsigned b0 = __float_as_uint(kv[(kk + t    ) * LDKV + w * 8 + g]);
            unsigned b1 = __float_as_uint(kv[(kk + t + 4) * LDKV + w * 8 + g]);
            int cb = kt * 64 + kk;
            unsigned a0 = __float_as_uint(ss[(g     ) * 580 + cb + t]);
            unsigned a1 = __float_as_uint(ss[(g +  8) * 580 + cb + t]);
            unsigned a2 = __float_as_uint(ss[(g     ) * 580 + cb + t + 4]);
            unsigned a3 = __float_as_uint(ss[(g +  8) * 580 + cb + t + 4]);
            mma8(p0, a0, a1, a2, a3, b0, b1);
            a0 = __float_as_uint(ss[(g + 16) * 580 + cb + t]);
            a1 = __float_as_uint(ss[(g + 24) * 580 + cb + t]);
            a2 = __float_as_uint(ss[(g + 16) * 580 + cb + t + 4]);
            a3 = __float_as_uint(ss[(g + 24) * 580 + cb + t + 4]);
            mma8(p1, a0, a1, a2, a3, b0, b1);
        }
    }

    // write ctx (tf32-rounded for the proj GEMM)
    {
        size_t bn = (size_t)b * Nq + n0;
        int d0 = w * 8 + 2 * t;
        size_t hofs = (size_t)h * DHq;
        g_ctx[(bn + g     ) * Cq + hofs + d0    ] = f2tff(p0[0]);
        g_ctx[(bn + g     ) * Cq + hofs + d0 + 1] = f2tff(p0[1]);
        g_ctx[(bn + g +  8) * Cq + hofs + d0    ] = f2tff(p0[2]);
        g_ctx[(bn + g +  8) * Cq + hofs + d0 + 1] = f2tff(p0[3]);
        g_ctx[(bn + g + 16) * Cq + hofs + d0    ] = f2tff(p1[0]);
        g_ctx[(bn + g + 16) * Cq + hofs + d0 + 1] = f2tff(p1[1]);
        g_ctx[(bn + g + 24) * Cq + hofs + d0    ] = f2tff(p1[2]);
        g_ctx[(bn + g + 24) * Cq + hofs + d0 + 1] = f2tff(p1[3]);
    }
}

// ---------------------------------------------------------------------------
extern "C" void kernel_launch(void* const* d_in, const int* in_sizes, int n_in,
                              void* d_out, int out_size)
{
    const float* x      = (const float*)d_in[0];
    const float* w_qk   = (const float*)d_in[1];
    const float* w_v    = (const float*)d_in[2];
    const float* w_proj = (const float*)d_in[3];
    const float* b_proj = (const float*)d_in[4];
    const float* w_pos  = (const float*)d_in[5];
    const float* b_pos  = (const float*)d_in[6];
    const float* gating = (const float*)d_in[7];
    float* out = (float*)d_out;

    cudaFuncSetAttribute(attn_tc, cudaFuncAttributeMaxDynamicSharedMemorySize,
                         SMEM_ATTN_BYTES);

    float* d_xt; cudaGetSymbolAddress((void**)&d_xt, g_xt);
    float* d_wqkt; cudaGetSymbolAddress((void**)&d_wqkt, g_wqkt);
    float* d_wvt; cudaGetSymbolAddress((void**)&d_wvt, g_wvt);
    float* d_wpt; cudaGetSymbolAddress((void**)&d_wpt, g_wpt);

    cvt_kernel<<<(7077888 / 4 + 255) / 256, 256>>>(x, d_xt, 7077888 / 4);
    cvt_kernel<<<(1179648 / 4 + 255) / 256, 256>>>(w_qk, d_wqkt, 1179648 / 4);
    cvt_kernel<<<(589824 / 4 + 255) / 256, 256>>>(w_v, d_wvt, 589824 / 4);
    cvt_kernel<<<(589824 / 4 + 255) / 256, 256>>>(w_proj, d_wpt, 589824 / 4);

    pos_kernel<<<dim3(Nq, Hq), 256>>>(w_pos, b_pos);
    gemm_qkv_tc<<<dim3(18, 72), 256>>>(out);
    attn_tc<<<dim3(18, Hq, Bq), 256, SMEM_ATTN_BYTES>>>(gating, out);
    gemm_proj_tc<<<dim3(6, 72), 256>>>(b_proj, out);
}